// round 1
// baseline (speedup 1.0000x reference)
#include <cuda_runtime.h>
#include <cstddef>

#define NPTS 1000000
#define KSZ 9
#define CCH 16
#define EPSBN 1e-5f
#define NF4 (NPTS * CCH / 4)          // 4,000,000 float4s
#define SGRID 1184                    // stats / elementwise grid (148 SMs * 8)
#define SSTRIDE (SGRID * 256)

// ---------------- scratch (device globals: no allocation) ----------------
__device__ float g_h[(size_t)NPTS * CCH];        // hidden activations (raw conv1 output), 64 MB
__device__ float4 g_part4[SGRID * 8];            // per-block stats partials: [blk][sum4 x4, sq4 x4]
__device__ __align__(16) float g_st1[32];        // BN1: scale[16], shift[16]
__device__ __align__(16) float g_st2[32];        // BN2: scale[16], shift[16]

__device__ __forceinline__ float leaky(float x) { return fmaxf(x, 0.2f * x); }

// ---------------- conv1: out_raw = gather(data) x w1 + b1 -> g_h ----------------
__global__ __launch_bounds__(256) void conv1_kernel(
    const float* __restrict__ data, const int* __restrict__ ind,
    const float* __restrict__ w, const float* __restrict__ bias)
{
    __shared__ float ws[KSZ * 256];   // ws[j][c][o]
    __shared__ float sb[CCH];
    const int tid = threadIdx.x;
    for (int i = tid; i < CCH * CCH * KSZ; i += 256) {
        int c = i / (CCH * KSZ);
        int rem = i - c * (CCH * KSZ);
        int o = rem / KSZ;
        int j = rem - o * KSZ;
        ws[j * 256 + c * 16 + o] = w[i];
    }
    if (tid < CCH) sb[tid] = bias[tid];
    __syncthreads();

    const int n = blockIdx.x * 256 + tid;
    if (n >= NPTS) return;

    float acc[16];
#pragma unroll
    for (int o = 0; o < 16; o++) acc[o] = sb[o];

    const int* ip = ind + (size_t)n * KSZ;
#pragma unroll
    for (int j = 0; j < KSZ; j++) {
        const int r = ip[j];
        const float4* dp = reinterpret_cast<const float4*>(data) + (size_t)r * 4;
        float4 a0 = dp[0], a1 = dp[1], a2 = dp[2], a3 = dp[3];
        float vv[16] = {a0.x, a0.y, a0.z, a0.w, a1.x, a1.y, a1.z, a1.w,
                        a2.x, a2.y, a2.z, a2.w, a3.x, a3.y, a3.z, a3.w};
        const float* wj = ws + j * 256;
#pragma unroll
        for (int c = 0; c < 16; c++) {
            const float v = vv[c];
#pragma unroll
            for (int o = 0; o < 16; o++)
                acc[o] = fmaf(v, wj[c * 16 + o], acc[o]);
        }
    }
    float4* op = reinterpret_cast<float4*>(g_h) + (size_t)n * 4;
    op[0] = make_float4(acc[0], acc[1], acc[2], acc[3]);
    op[1] = make_float4(acc[4], acc[5], acc[6], acc[7]);
    op[2] = make_float4(acc[8], acc[9], acc[10], acc[11]);
    op[3] = make_float4(acc[12], acc[13], acc[14], acc[15]);
}

// ------- conv2: gather g_h, apply BN1+leaky inline, x w2 -> raw2 (d_out) -------
__global__ __launch_bounds__(256) void conv2_kernel(
    const int* __restrict__ ind, const float* __restrict__ w,
    float* __restrict__ dst)
{
    __shared__ float ws[KSZ * 256];
    __shared__ float bsc[CCH], bsh[CCH];
    const int tid = threadIdx.x;
    for (int i = tid; i < CCH * CCH * KSZ; i += 256) {
        int c = i / (CCH * KSZ);
        int rem = i - c * (CCH * KSZ);
        int o = rem / KSZ;
        int j = rem - o * KSZ;
        ws[j * 256 + c * 16 + o] = w[i];
    }
    if (tid < CCH) { bsc[tid] = g_st1[tid]; bsh[tid] = g_st1[16 + tid]; }
    __syncthreads();

    const int n = blockIdx.x * 256 + tid;
    if (n >= NPTS) return;

    float acc[16];
#pragma unroll
    for (int o = 0; o < 16; o++) acc[o] = 0.0f;

    const int* ip = ind + (size_t)n * KSZ;
#pragma unroll
    for (int j = 0; j < KSZ; j++) {
        const int r = ip[j];
        const float4* dp = reinterpret_cast<const float4*>(g_h) + (size_t)r * 4;
        float4 a0 = dp[0], a1 = dp[1], a2 = dp[2], a3 = dp[3];
        float vv[16] = {a0.x, a0.y, a0.z, a0.w, a1.x, a1.y, a1.z, a1.w,
                        a2.x, a2.y, a2.z, a2.w, a3.x, a3.y, a3.z, a3.w};
        const float* wj = ws + j * 256;
#pragma unroll
        for (int c = 0; c < 16; c++) {
            const float v = leaky(fmaf(vv[c], bsc[c], bsh[c]));
#pragma unroll
            for (int o = 0; o < 16; o++)
                acc[o] = fmaf(v, wj[c * 16 + o], acc[o]);
        }
    }
    float4* op = reinterpret_cast<float4*>(dst) + (size_t)n * 4;
    op[0] = make_float4(acc[0], acc[1], acc[2], acc[3]);
    op[1] = make_float4(acc[4], acc[5], acc[6], acc[7]);
    op[2] = make_float4(acc[8], acc[9], acc[10], acc[11]);
    op[3] = make_float4(acc[12], acc[13], acc[14], acc[15]);
}

// ---------------- stats pass: per-block partial sum / sumsq per channel ----------------
// Each thread's float4 covers a fixed channel group g = tid%4 (stride is a multiple of 4).
__global__ __launch_bounds__(256) void stats_kernel(const float* __restrict__ xin)
{
    const float4* x = reinterpret_cast<const float4*>(xin ? xin : g_h);
    const int tid = threadIdx.x;
    int idx = blockIdx.x * 256 + tid;
    float4 s = make_float4(0.f, 0.f, 0.f, 0.f);
    float4 q = make_float4(0.f, 0.f, 0.f, 0.f);
    for (int i = idx; i < NF4; i += SSTRIDE) {
        float4 v = x[i];
        s.x += v.x; s.y += v.y; s.z += v.z; s.w += v.w;
        q.x += v.x * v.x; q.y += v.y * v.y; q.z += v.z * v.z; q.w += v.w * v.w;
    }
    __shared__ float4 s1[256], s2[256];
    s1[tid] = s; s2[tid] = q;
    __syncthreads();
#pragma unroll
    for (int off = 128; off >= 4; off >>= 1) {
        if (tid < off) {
            float4 a = s1[tid], b = s1[tid + off];
            a.x += b.x; a.y += b.y; a.z += b.z; a.w += b.w; s1[tid] = a;
            float4 c = s2[tid], d = s2[tid + off];
            c.x += d.x; c.y += d.y; c.z += d.z; c.w += d.w; s2[tid] = c;
        }
        __syncthreads();
    }
    if (tid < 4) {
        g_part4[blockIdx.x * 8 + tid] = s1[tid];        // channels 4*tid..4*tid+3, sums
        g_part4[blockIdx.x * 8 + 4 + tid] = s2[tid];    // squares
    }
}

// ------------- finalize: reduce partials -> per-channel BN scale/shift -------------
template <int S>
__global__ __launch_bounds__(256) void finalize_kernel(
    const float* __restrict__ gamma, const float* __restrict__ beta)
{
    const int tid = threadIdx.x;
    const int v = tid & 31;         // which of 32 stats values
    const int lane = tid >> 5;      // 8 chunks over blocks
    const float* part = reinterpret_cast<const float*>(g_part4);
    float loc = 0.f;
    for (int r = lane; r < SGRID; r += 8) loc += part[r * 32 + v];
    __shared__ float sm[256];
    sm[tid] = loc;
    __syncthreads();
    if (tid < 32) {
        float t = 0.f;
#pragma unroll
        for (int k = 0; k < 8; k++) t += sm[v + k * 32];
        sm[v] = t;
    }
    __syncthreads();
    if (tid < 16) {
        const float inv_n = 1.0f / (float)NPTS;
        float mean = sm[tid] * inv_n;
        float var = sm[16 + tid] * inv_n - mean * mean;
        float rstd = rsqrtf(var + EPSBN);
        float sc = gamma[tid] * rstd;
        float sh = beta[tid] - mean * sc;
        float* st = (S == 1) ? g_st1 : g_st2;
        st[tid] = sc;
        st[16 + tid] = sh;
    }
}

// ------------- epilogue: out = leaky(BN2(raw2) + data), in place on d_out -------------
__global__ __launch_bounds__(256) void bnres_kernel(
    const float* __restrict__ data, float* __restrict__ out)
{
    const int tid = threadIdx.x;
    const int idx = blockIdx.x * 256 + tid;
    const int g = tid & 3;  // fixed channel group per thread
    float4 sc = reinterpret_cast<const float4*>(g_st2)[g];
    float4 sh = reinterpret_cast<const float4*>(g_st2 + 16)[g];
    const float4* dd = reinterpret_cast<const float4*>(data);
    float4* oo = reinterpret_cast<float4*>(out);
    for (int i = idx; i < NF4; i += SSTRIDE) {
        float4 r = oo[i];
        float4 d = dd[i];
        float4 y;
        y.x = fmaf(r.x, sc.x, sh.x) + d.x;
        y.y = fmaf(r.y, sc.y, sh.y) + d.y;
        y.z = fmaf(r.z, sc.z, sh.z) + d.z;
        y.w = fmaf(r.w, sc.w, sh.w) + d.w;
        y.x = fmaxf(y.x, 0.2f * y.x);
        y.y = fmaxf(y.y, 0.2f * y.y);
        y.z = fmaxf(y.z, 0.2f * y.z);
        y.w = fmaxf(y.w, 0.2f * y.w);
        oo[i] = y;
    }
}

extern "C" void kernel_launch(void* const* d_in, const int* in_sizes, int n_in,
                              void* d_out, int out_size)
{
    const float* data   = (const float*)d_in[0];
    const int*   ind    = (const int*)  d_in[1];
    const float* w1     = (const float*)d_in[2];
    const float* b1     = (const float*)d_in[3];
    const float* gamma1 = (const float*)d_in[4];
    const float* beta1  = (const float*)d_in[5];
    const float* w2     = (const float*)d_in[6];
    const float* gamma2 = (const float*)d_in[7];
    const float* beta2  = (const float*)d_in[8];
    float* out = (float*)d_out;

    const int conv_grid = (NPTS + 255) / 256;   // 3907

    conv1_kernel<<<conv_grid, 256>>>(data, ind, w1, b1);
    stats_kernel<<<SGRID, 256>>>(nullptr);                 // stats of g_h
    finalize_kernel<1><<<1, 256>>>(gamma1, beta1);
    conv2_kernel<<<conv_grid, 256>>>(ind, w2, out);        // BN1+leaky fused into gather
    stats_kernel<<<SGRID, 256>>>(out);                     // stats of raw2
    finalize_kernel<2><<<1, 256>>>(gamma2, beta2);
    bnres_kernel<<<SGRID, 256>>>(data, out);               // BN2 + residual + leaky
}